// round 6
// baseline (speedup 1.0000x reference)
#include <cuda_runtime.h>
#include <cuda_bf16.h>

// Problem constants (match reference)
#define DT_C      0.01f
#define MIN_VAR   0.01f
#define REG_W     0.01
#define EPS_L     1e-6f
#define BATCH     256
#define TLEN      16384
#define NTHREADS  1024
#define NCHUNKS   (TLEN / NTHREADS)   // 16

// Global accumulators: [0]=lv_p sum, [1]=lv_e sum, [2]=lc sum (mahal+logdet), [3]=reg sum
__device__ double g_acc[4];

__global__ void zero_acc_kernel() {
    if (threadIdx.x < 4) g_acc[threadIdx.x] = 0.0;
}

__global__ __launch_bounds__(NTHREADS, 2)
void mtl_main_kernel(const float2* __restrict__ vel,
                     const float2* __restrict__ cov,
                     const float2* __restrict__ vgt,
                     const float2* __restrict__ pgt)
{
    __shared__ float2 wsum[32];
    __shared__ float4 sred[32];

    const int b    = blockIdx.x;
    const int lane = threadIdx.x & 31;
    const int wid  = threadIdx.x >> 5;
    const long base = (long)b * TLEN;   // float2 index of row start

    // vel_pred[b, 0, :] — same address for all threads: L1 broadcast
    const float2 v0 = vel[base];

    float carry_x = 0.0f, carry_y = 0.0f;   // exclusive prefix entering this chunk
    float lvp = 0.0f, lve = 0.0f, lcs = 0.0f, rgs = 0.0f;

    #pragma unroll 1
    for (int chunk = 0; chunk < NCHUNKS; ++chunk) {
        const long idx = base + chunk * NTHREADS + threadIdx.x;

        // Issue all 4 loads up front (independent -> MLP=4)
        const float2 v = vel[idx];
        const float2 c = cov[idx];
        const float2 g = vgt[idx];
        const float2 p = pgt[idx];

        // ---- warp-level inclusive scan of (v.x, v.y) ----
        float x = v.x, y = v.y;
        #pragma unroll
        for (int off = 1; off < 32; off <<= 1) {
            float nx = __shfl_up_sync(0xffffffffu, x, off);
            float ny = __shfl_up_sync(0xffffffffu, y, off);
            if (lane >= off) { x += nx; y += ny; }
        }
        if (lane == 31) wsum[wid] = make_float2(x, y);
        __syncthreads();

        // ---- cross-warp scan (32 warp totals) by warp 0 ----
        if (wid == 0) {
            float sx = wsum[lane].x, sy = wsum[lane].y;
            #pragma unroll
            for (int off = 1; off < 32; off <<= 1) {
                float nx = __shfl_up_sync(0xffffffffu, sx, off);
                float ny = __shfl_up_sync(0xffffffffu, sy, off);
                if (lane >= off) { sx += nx; sy += ny; }
            }
            wsum[lane] = make_float2(sx, sy);  // inclusive prefix of warp totals
        }
        __syncthreads();

        float pre_x = carry_x, pre_y = carry_y;
        if (wid > 0) { pre_x += wsum[wid - 1].x; pre_y += wsum[wid - 1].y; }
        // chunk total for next iteration's carry
        carry_x += wsum[31].x;
        carry_y += wsum[31].y;
        __syncthreads();   // protect wsum before next chunk's writes

        // exclusive global prefix at t = pre + (inclusive - self)
        const float ex = pre_x + (x - v.x);
        const float ey = pre_y + (y - v.y);

        // pos_pred[t] = DT * (vel[0] + exclusive_prefix[t])
        const float posx = DT_C * (v0.x + ex);
        const float posy = DT_C * (v0.y + ey);

        const float dpx = posx - p.x, dpy = posy - p.y;
        lvp += dpx * dpx + dpy * dpy;

        const float dvx = v.x - g.x, dvy = v.y - g.y;   // (pred - gt)^2 == (gt - pred)^2
        lve += dvx * dvx + dvy * dvy;

        const float sgx = fmaxf(__expf(c.x), MIN_VAR);
        const float sgy = fmaxf(__expf(c.y), MIN_VAR);
        const float ivx = __frcp_rn(sgx);
        const float ivy = __frcp_rn(sgy);
        const float mahal  = ivx * dvx * dvx + ivy * dvy * dvy;
        const float logdet = __logf(sgx * sgy + EPS_L);
        lcs += mahal + logdet;
        rgs += ivx + ivy;
    }

    // ---- block reduction of the 4 partial sums ----
    float4 acc = make_float4(lvp, lve, lcs, rgs);
    #pragma unroll
    for (int off = 16; off > 0; off >>= 1) {
        acc.x += __shfl_down_sync(0xffffffffu, acc.x, off);
        acc.y += __shfl_down_sync(0xffffffffu, acc.y, off);
        acc.z += __shfl_down_sync(0xffffffffu, acc.z, off);
        acc.w += __shfl_down_sync(0xffffffffu, acc.w, off);
    }
    if (lane == 0) sred[wid] = acc;
    __syncthreads();
    if (wid == 0) {
        acc = sred[lane];
        #pragma unroll
        for (int off = 16; off > 0; off >>= 1) {
            acc.x += __shfl_down_sync(0xffffffffu, acc.x, off);
            acc.y += __shfl_down_sync(0xffffffffu, acc.y, off);
            acc.z += __shfl_down_sync(0xffffffffu, acc.z, off);
            acc.w += __shfl_down_sync(0xffffffffu, acc.w, off);
        }
        if (lane == 0) {
            atomicAdd(&g_acc[0], (double)acc.x);
            atomicAdd(&g_acc[1], (double)acc.y);
            atomicAdd(&g_acc[2], (double)acc.z);
            atomicAdd(&g_acc[3], (double)acc.w);
        }
    }
}

__global__ void mtl_finalize_kernel(const float* __restrict__ log_dv_p,
                                    const float* __restrict__ log_dc_p,
                                    float* __restrict__ out)
{
    const double n_all = (double)BATCH * (double)TLEN * 2.0;  // elements for lv means
    const double n_bt  = (double)BATCH * (double)TLEN;        // elements for lc/reg means

    const float  ldv = *log_dv_p;
    const float  ldc = *log_dc_p;
    const double dv  = exp((double)ldv);
    const double dc  = exp((double)ldc);

    const double lv_total = g_acc[0] / n_all + g_acc[1] / n_all;
    const double lc_total = 0.5 * (g_acc[2] / n_bt);
    const double reg      = g_acc[3] / n_bt;

    double total = lv_total / (2.0 * dv * dv)
                 + lc_total / (2.0 * dc * dc)
                 + (double)ldv + (double)ldc
                 + REG_W * reg;

    *out = (float)total;
}

extern "C" void kernel_launch(void* const* d_in, const int* in_sizes, int n_in,
                              void* d_out, int out_size)
{
    const float2* vel = (const float2*)d_in[0];   // vel_pred [B,T,2]
    const float2* cov = (const float2*)d_in[1];   // cov_pred [B,T,2]
    const float2* vgt = (const float2*)d_in[2];   // vel_gt   [B,T,2]
    const float2* pgt = (const float2*)d_in[3];   // pos_gt   [B,T,2]
    const float*  ldv = (const float*)d_in[4];    // log_delta_v scalar
    const float*  ldc = (const float*)d_in[5];    // log_delta_c scalar
    float* out = (float*)d_out;

    zero_acc_kernel<<<1, 32>>>();
    mtl_main_kernel<<<BATCH, NTHREADS>>>(vel, cov, vgt, pgt);
    mtl_finalize_kernel<<<1, 1>>>(ldv, ldc, out);
}